// round 11
// baseline (speedup 1.0000x reference)
#include <cuda_runtime.h>
#include <cuda_bf16.h>
#include <cstdint>

// NODE forest via mma.sync bf16 (plain compute_103 PTX).
// R11: two-phase CTA. Phase 1 streams x through a bf16 hi/lo split into
// smem (high MLP, coalesced LDG, no MMA deps). Phase 2 is a pure LDS+HMMA
// mainloop (no cvt in the chain). 256 thr, SPB=256, 2 CTAs/SM.
//
// Numerics (proven R9/R10): 3-pass bf16 split (Ah*Wh + Ah*Wl + Al*Wh, fp32
// accum), error <= ~3e-4 << TAU=2e-3; |z|<=TAU recomputed with the exact
// fp32 ascending-i FMA chain from GLOBAL x/W, bias after,
// bit = fl(0.5 + 0.25 z) > 0.5 (XLA rule) -> leaf indices bit-identical.

#define THREADS 256
#define SPB 256
#define NBLK 4096
#define TAU 2e-3f

// ---- shared layout (bytes) ----
// Xh  : u32[256][36] = 36864 @ 0       (bf16x2 pairs, slot-rotated)
// Xl  : u32[256][36] = 36864 @ 36864
// Whp : u32[48][36]  =  6912 @ 73728
// Wlp : u32[48][36]  =  6912 @ 80640
// tbl : float2[512]  =  4096 @ 87552
// bs  : f32[48]      =   192 @ 91648
#define XH_OFF   0
#define XL_OFF   36864
#define WHP_OFF  73728
#define WLP_OFF  80640
#define TBL_OFF  87552
#define BS_OFF   91648
#define SMEM_BYTES 91840

static __device__ __forceinline__ uint32_t bf16x2_rn(float hi, float lo) {
    uint32_t r;
    asm("cvt.rn.bf16x2.f32 %0, %1, %2;" : "=r"(r) : "f"(hi), "f"(lo));
    return r;
}
static __device__ __forceinline__ void split2(float vx, float vy,
                                              uint32_t& h, uint32_t& l) {
    h = bf16x2_rn(vy, vx);
    float h0 = __uint_as_float(h << 16);
    float h1 = __uint_as_float(h & 0xffff0000u);
    l = bf16x2_rn(vy - h1, vx - h0);
}
static __device__ __forceinline__ void mma_bf16(float* c, const uint32_t* a,
                                                const uint32_t* b) {
    asm("mma.sync.aligned.m16n8k16.row.col.f32.bf16.bf16.f32 "
        "{%0,%1,%2,%3}, {%4,%5,%6,%7}, {%8,%9}, {%0,%1,%2,%3};"
        : "+f"(c[0]), "+f"(c[1]), "+f"(c[2]), "+f"(c[3])
        : "r"(a[0]), "r"(a[1]), "r"(a[2]), "r"(a[3]), "r"(b[0]), "r"(b[1]));
}
static __device__ __forceinline__ int xla_bit(float z) {
    return __fadd_rn(0.5f, __fmul_rn(0.25f, z)) > 0.5f;
}

__global__ __launch_bounds__(THREADS, 2)
void node_forest_mma_kernel(const float*  __restrict__ x,      // [B,64]
                            const float*  __restrict__ Wsel,   // [48,64]
                            const float*  __restrict__ bsel,   // [48]
                            const float*  __restrict__ leafv,  // [8,64,2]
                            const float*  __restrict__ fcw,    // [2,16]
                            const float*  __restrict__ fcb,    // [2]
                            float2*       __restrict__ out)    // [B]
{
    extern __shared__ unsigned char smem[];
    uint32_t* Xh  = (uint32_t*)(smem + XH_OFF);
    uint32_t* Xl  = (uint32_t*)(smem + XL_OFF);
    uint32_t* Whp = (uint32_t*)(smem + WHP_OFF);
    uint32_t* Wlp = (uint32_t*)(smem + WLP_OFF);
    float2*   tbl = (float2*)(smem + TBL_OFF);
    float*    bs  = (float*)(smem + BS_OFF);

    const int tid = threadIdx.x;

    // ---- phase 1a: W hi/lo packed tiles ----
    #pragma unroll
    for (int e = tid; e < 1536; e += THREADS) {
        int d = e >> 5, ip = e & 31;
        float2 wp = *(const float2*)(Wsel + d * 64 + 2 * ip);
        uint32_t h, l;
        split2(wp.x, wp.y, h, l);
        Whp[d * 36 + ip] = h;
        Wlp[d * 36 + ip] = l;
    }
    // ---- phase 1b: leaf table fold + bias ----
    #pragma unroll
    for (int e = tid; e < 512; e += THREADS) {
        int t = e >> 6, leaf = e & 63;
        float l0 = leafv[t * 128 + leaf * 2 + 0];
        float l1 = leafv[t * 128 + leaf * 2 + 1];
        tbl[e] = make_float2(l0 * fcw[t * 2]      + l1 * fcw[t * 2 + 1],
                             l0 * fcw[16 + t * 2] + l1 * fcw[16 + t * 2 + 1]);
    }
    if (tid < 48) bs[tid] = bsel[tid];

    // ---- phase 1c: stream x -> split -> smem (coalesced LDG, MLP=16) ----
    const float4* xg = (const float4*)x + (size_t)blockIdx.x * (SPB * 16);
    #pragma unroll
    for (int it = 0; it < 16; ++it) {
        int f = tid + it * THREADS;       // float4 index (0..4095)
        float4 v = xg[f];
        int s = f >> 4, c = f & 15;       // row, float4-column
        int rot = s >> 3;
        uint32_t h0, l0, h1, l1;
        split2(v.x, v.y, h0, l0);
        split2(v.z, v.w, h1, l1);
        int base = s * 36;
        int s0 = (2 * c     + rot) & 31;
        int s1 = (2 * c + 1 + rot) & 31;
        Xh[base + s0] = h0;  Xh[base + s1] = h1;
        Xl[base + s0] = l0;  Xl[base + s1] = l1;
    }
    __syncthreads();

    const int lane = tid & 31, w = tid >> 5;
    const int g = lane >> 2, tig = lane & 3;
    const float* gx = x + (size_t)blockIdx.x * (SPB * 64);

    float acc[2][6][4];
    #pragma unroll
    for (int m = 0; m < 2; ++m)
        #pragma unroll
        for (int n = 0; n < 6; ++n)
            #pragma unroll
            for (int q = 0; q < 4; ++q) acc[m][n][q] = 0.f;

    // ---- phase 2: pure LDS + HMMA mainloop ----
    #pragma unroll
    for (int kt = 0; kt < 4; ++kt) {
        uint32_t bh[6][2], bl[6][2];
        #pragma unroll
        for (int n = 0; n < 6; ++n) {
            int ip0 = (n * 8 + g) * 36 + kt * 8 + tig;
            bh[n][0] = Whp[ip0];  bh[n][1] = Whp[ip0 + 4];
            bl[n][0] = Wlp[ip0];  bl[n][1] = Wlp[ip0 + 4];
        }
        #pragma unroll
        for (int m = 0; m < 2; ++m) {
            int ra = w * 32 + m * 16 + g;
            int rb = ra + 8;
            int rota = (w * 32 + m * 16) >> 3;   // == ra>>3 (g < 8)
            int rotb = rota + 1;
            int P = kt * 8 + tig;
            uint32_t ah[4], al[4];
            int ia0 = ra * 36 + ((P     + rota) & 31);
            int ia2 = ra * 36 + ((P + 4 + rota) & 31);
            int ib1 = rb * 36 + ((P     + rotb) & 31);
            int ib3 = rb * 36 + ((P + 4 + rotb) & 31);
            ah[0] = Xh[ia0];  ah[1] = Xh[ib1];
            ah[2] = Xh[ia2];  ah[3] = Xh[ib3];
            al[0] = Xl[ia0];  al[1] = Xl[ib1];
            al[2] = Xl[ia2];  al[3] = Xl[ib3];
            #pragma unroll
            for (int n = 0; n < 6; ++n) {
                mma_bf16(acc[m][n], ah, bh[n]);
                mma_bf16(acc[m][n], ah, bl[n]);
                mma_bf16(acc[m][n], al, bh[n]);
            }
        }
    }

    // ---- epilogue: bias, recompute band (global, rare), bit masks ----
    unsigned long long mask[2][2] = {{0ull, 0ull}, {0ull, 0ull}};
    #pragma unroll
    for (int m = 0; m < 2; ++m) {
        #pragma unroll
        for (int half = 0; half < 2; ++half) {
            int row = w * 32 + m * 16 + half * 8 + g;
            #pragma unroll
            for (int n = 0; n < 6; ++n) {
                #pragma unroll
                for (int e = 0; e < 2; ++e) {
                    int col = n * 8 + tig * 2 + e;
                    float z = __fadd_rn(acc[m][n][2 * half + e], bs[col]);
                    if (fabsf(z) <= TAU) {
                        const float* xr = gx + row * 64;
                        const float* wr = Wsel + col * 64;
                        float a = 0.f;
                        #pragma unroll 1
                        for (int i = 0; i < 64; ++i)
                            a = __fmaf_rn(__ldg(xr + i), __ldg(wr + i), a);
                        z = __fadd_rn(a, bs[col]);
                    }
                    mask[m][half] |= ((unsigned long long)xla_bit(z)) << col;
                }
            }
        }
    }
    #pragma unroll
    for (int m = 0; m < 2; ++m)
        #pragma unroll
        for (int half = 0; half < 2; ++half) {
            unsigned long long v = mask[m][half];
            v |= __shfl_xor_sync(0xffffffffu, v, 1);
            v |= __shfl_xor_sync(0xffffffffu, v, 2);
            mask[m][half] = v;
        }

    const unsigned long long mk = mask[tig >> 1][tig & 1];
    const int row = w * 32 + (tig >> 1) * 16 + (tig & 1) * 8 + g;
    float o0 = __ldg(&fcb[0]), o1 = __ldg(&fcb[1]);
    #pragma unroll
    for (int t = 0; t < 8; ++t) {
        int bits6 = (int)(mk >> (6 * t)) & 63;
        int leaf = __brev((unsigned)bits6) >> 26;
        float2 tv = tbl[t * 64 + leaf];
        o0 += tv.x;
        o1 += tv.y;
    }
    out[(size_t)blockIdx.x * SPB + row] = make_float2(o0, o1);
}

extern "C" void kernel_launch(void* const* d_in, const int* in_sizes, int n_in,
                              void* d_out, int out_size) {
    (void)in_sizes; (void)n_in; (void)out_size;
    cudaFuncSetAttribute(node_forest_mma_kernel,
                         cudaFuncAttributeMaxDynamicSharedMemorySize, SMEM_BYTES);
    cudaFuncSetAttribute(node_forest_mma_kernel,
                         cudaFuncAttributePreferredSharedMemoryCarveout, 100);
    node_forest_mma_kernel<<<NBLK, THREADS, SMEM_BYTES>>>(
        (const float*)d_in[0],   // x
        (const float*)d_in[1],   // W_sel
        (const float*)d_in[2],   // b_sel
        (const float*)d_in[3],   // leaf_values
        (const float*)d_in[4],   // fc_w
        (const float*)d_in[5],   // fc_b
        (float2*)d_out);
}

// round 12
// speedup vs baseline: 1.8970x; 1.8970x over previous
#include <cuda_runtime.h>
#include <cuda_bf16.h>
#include <cstdint>

// NODE forest via mma.sync bf16 (plain compute_103 PTX).
// R12 = R10 skeleton with latency fixes:
//  - all 32 global x loads of a 128-row tile batched first (MLP 32)
//  - 4 M-tiles per CTA (prologue amortized; cross-tile overlap)
//  - lean smem (18KB), __launch_bounds__(128,3)
//
// Numerics (proven R9-R11, rel_err 9.2e-8): 3-pass bf16 split
// (Ah*Wh + Ah*Wl + Al*Wh, fp32 accum), error <= ~1e-4 << TAU=2e-3;
// |z|<=TAU recomputed with the exact fp32 ascending-i FMA chain from
// global x/W, bias after, bit = fl(0.5 + 0.25 z) > 0.5 (XLA rule).

#define THREADS 128
#define TILES 4
#define NBLK 2048          // 1048576 / (4*128)
#define TAU 2e-3f

// ---- shared layout (bytes) ----
#define WHP_OFF  0         // u32[48][36] = 6912
#define WLP_OFF  6912      // u32[48][36] = 6912
#define TBL_OFF  13824     // float2[512] = 4096
#define BS_OFF   17920     // f32[48]     =  192
#define SMEM_BYTES 18112

static __device__ __forceinline__ uint32_t bf16x2_rn(float hi, float lo) {
    uint32_t r;
    asm("cvt.rn.bf16x2.f32 %0, %1, %2;" : "=r"(r) : "f"(hi), "f"(lo));
    return r;
}
static __device__ __forceinline__ void split2(float vx, float vy,
                                              uint32_t& h, uint32_t& l) {
    h = bf16x2_rn(vy, vx);
    float h0 = __uint_as_float(h << 16);
    float h1 = __uint_as_float(h & 0xffff0000u);
    l = bf16x2_rn(vy - h1, vx - h0);
}
static __device__ __forceinline__ void mma_bf16(float* c, const uint32_t* a,
                                                const uint32_t* b) {
    asm("mma.sync.aligned.m16n8k16.row.col.f32.bf16.bf16.f32 "
        "{%0,%1,%2,%3}, {%4,%5,%6,%7}, {%8,%9}, {%0,%1,%2,%3};"
        : "+f"(c[0]), "+f"(c[1]), "+f"(c[2]), "+f"(c[3])
        : "r"(a[0]), "r"(a[1]), "r"(a[2]), "r"(a[3]), "r"(b[0]), "r"(b[1]));
}
static __device__ __forceinline__ int xla_bit(float z) {
    return __fadd_rn(0.5f, __fmul_rn(0.25f, z)) > 0.5f;
}

__global__ __launch_bounds__(THREADS, 3)
void node_forest_mma_kernel(const float*  __restrict__ x,      // [B,64]
                            const float*  __restrict__ Wsel,   // [48,64]
                            const float*  __restrict__ bsel,   // [48]
                            const float*  __restrict__ leafv,  // [8,64,2]
                            const float*  __restrict__ fcw,    // [2,16]
                            const float*  __restrict__ fcb,    // [2]
                            float2*       __restrict__ out)    // [B]
{
    extern __shared__ unsigned char smem[];
    uint32_t* Whp = (uint32_t*)(smem + WHP_OFF);
    uint32_t* Wlp = (uint32_t*)(smem + WLP_OFF);
    float2*   tbl = (float2*)(smem + TBL_OFF);
    float*    bs  = (float*)(smem + BS_OFF);

    const int tid = threadIdx.x;

    // ---- prologue: W hi/lo tiles, leaf table fold, bias (once per CTA) ----
    #pragma unroll
    for (int e = tid; e < 1536; e += THREADS) {
        int d = e >> 5, ip = e & 31;
        float2 wp = *(const float2*)(Wsel + d * 64 + 2 * ip);
        uint32_t h, l;
        split2(wp.x, wp.y, h, l);
        Whp[d * 36 + ip] = h;
        Wlp[d * 36 + ip] = l;
    }
    #pragma unroll
    for (int e = tid; e < 512; e += THREADS) {
        int t = e >> 6, leaf = e & 63;
        float l0 = leafv[t * 128 + leaf * 2 + 0];
        float l1 = leafv[t * 128 + leaf * 2 + 1];
        tbl[e] = make_float2(l0 * fcw[t * 2]      + l1 * fcw[t * 2 + 1],
                             l0 * fcw[16 + t * 2] + l1 * fcw[16 + t * 2 + 1]);
    }
    if (tid < 48) bs[tid] = bsel[tid];
    __syncthreads();

    const int lane = tid & 31, w = tid >> 5;
    const int g = lane >> 2, tig = lane & 3;
    const float fb0 = __ldg(&fcb[0]), fb1 = __ldg(&fcb[1]);

    #pragma unroll 1
    for (int tt = 0; tt < TILES; ++tt) {
        const size_t tile = (size_t)blockIdx.x * TILES + tt;
        const float* gxt = x + (tile << 13);            // tile * 128 * 64

        // ---- batch ALL 32 global float2 loads for this tile (MLP 32) ----
        float2 raw[2][16];
        #pragma unroll
        for (int m = 0; m < 2; ++m) {
            int ra = w * 32 + m * 16 + g, rb = ra + 8;
            #pragma unroll
            for (int kt = 0; kt < 4; ++kt) {
                int c0 = kt * 16 + tig * 2;
                raw[m][kt * 4 + 0] = *(const float2*)(gxt + ra * 64 + c0);
                raw[m][kt * 4 + 1] = *(const float2*)(gxt + rb * 64 + c0);
                raw[m][kt * 4 + 2] = *(const float2*)(gxt + ra * 64 + c0 + 8);
                raw[m][kt * 4 + 3] = *(const float2*)(gxt + rb * 64 + c0 + 8);
            }
        }

        float acc[2][6][4];
        #pragma unroll
        for (int m = 0; m < 2; ++m)
            #pragma unroll
            for (int n = 0; n < 6; ++n)
                #pragma unroll
                for (int q = 0; q < 4; ++q) acc[m][n][q] = 0.f;

        // ---- mainloop: convert from regs + HMMA ----
        #pragma unroll
        for (int kt = 0; kt < 4; ++kt) {
            uint32_t bh[6][2], bl[6][2];
            #pragma unroll
            for (int n = 0; n < 6; ++n) {
                int ip0 = (n * 8 + g) * 36 + kt * 8 + tig;
                bh[n][0] = Whp[ip0];  bh[n][1] = Whp[ip0 + 4];
                bl[n][0] = Wlp[ip0];  bl[n][1] = Wlp[ip0 + 4];
            }
            #pragma unroll
            for (int m = 0; m < 2; ++m) {
                uint32_t ah[4], al[4];
                #pragma unroll
                for (int q = 0; q < 4; ++q)
                    split2(raw[m][kt * 4 + q].x, raw[m][kt * 4 + q].y,
                           ah[q], al[q]);
                #pragma unroll
                for (int n = 0; n < 6; ++n) {
                    mma_bf16(acc[m][n], ah, bh[n]);
                    mma_bf16(acc[m][n], ah, bl[n]);
                    mma_bf16(acc[m][n], al, bh[n]);
                }
            }
        }

        // ---- epilogue: bias, recompute band (rare), bit masks ----
        unsigned long long mask[2][2] = {{0ull, 0ull}, {0ull, 0ull}};
        #pragma unroll
        for (int m = 0; m < 2; ++m) {
            #pragma unroll
            for (int half = 0; half < 2; ++half) {
                int row = w * 32 + m * 16 + half * 8 + g;
                #pragma unroll
                for (int n = 0; n < 6; ++n) {
                    #pragma unroll
                    for (int e = 0; e < 2; ++e) {
                        int col = n * 8 + tig * 2 + e;
                        float z = __fadd_rn(acc[m][n][2 * half + e], bs[col]);
                        if (fabsf(z) <= TAU) {
                            // exact fp32 ascending-i chain (bit-faithful)
                            const float4* xr = (const float4*)(gxt + row * 64);
                            const float4* wr = (const float4*)(Wsel + col * 64);
                            float a = 0.f;
                            #pragma unroll 1
                            for (int i4 = 0; i4 < 16; ++i4) {
                                float4 xa = __ldg(xr + i4);
                                float4 wa = __ldg(wr + i4);
                                a = __fmaf_rn(xa.x, wa.x, a);
                                a = __fmaf_rn(xa.y, wa.y, a);
                                a = __fmaf_rn(xa.z, wa.z, a);
                                a = __fmaf_rn(xa.w, wa.w, a);
                            }
                            z = __fadd_rn(a, bs[col]);
                        }
                        mask[m][half] |=
                            ((unsigned long long)xla_bit(z)) << col;
                    }
                }
            }
        }
        #pragma unroll
        for (int m = 0; m < 2; ++m)
            #pragma unroll
            for (int half = 0; half < 2; ++half) {
                unsigned long long v = mask[m][half];
                v |= __shfl_xor_sync(0xffffffffu, v, 1);
                v |= __shfl_xor_sync(0xffffffffu, v, 2);
                mask[m][half] = v;
            }

        const unsigned long long mk = mask[tig >> 1][tig & 1];
        const int row = w * 32 + (tig >> 1) * 16 + (tig & 1) * 8 + g;
        float o0 = fb0, o1 = fb1;
        #pragma unroll
        for (int t = 0; t < 8; ++t) {
            int bits6 = (int)(mk >> (6 * t)) & 63;
            int leaf = __brev((unsigned)bits6) >> 26;
            float2 tv = tbl[t * 64 + leaf];
            o0 += tv.x;
            o1 += tv.y;
        }
        out[tile * 128 + row] = make_float2(o0, o1);
    }
}

extern "C" void kernel_launch(void* const* d_in, const int* in_sizes, int n_in,
                              void* d_out, int out_size) {
    (void)in_sizes; (void)n_in; (void)out_size;
    cudaFuncSetAttribute(node_forest_mma_kernel,
                         cudaFuncAttributeMaxDynamicSharedMemorySize, SMEM_BYTES);
    node_forest_mma_kernel<<<NBLK, THREADS, SMEM_BYTES>>>(
        (const float*)d_in[0],   // x
        (const float*)d_in[1],   // W_sel
        (const float*)d_in[2],   // b_sel
        (const float*)d_in[3],   // leaf_values
        (const float*)d_in[4],   // fc_w
        (const float*)d_in[5],   // fc_b
        (float2*)d_out);
}

// round 13
// speedup vs baseline: 2.2088x; 1.1643x over previous
#include <cuda_runtime.h>
#include <cuda_bf16.h>
#include <cstdint>

// NODE forest via mma.sync bf16 (plain compute_103 PTX).
// R13: cp.async double-buffered x pipeline (zero reg cost, true load/MMA
// overlap), M=64 tiles x 16 per CTA, 4 CTAs/SM, TAU tightened to the
// provably-safe 5e-4 (hard split-error bound 2.6e-4).
//
// Numerics (proven R9-R12, rel_err 9.2e-8): 3-pass bf16 split
// (Ah*Wh + Ah*Wl + Al*Wh, fp32 accum); |z|<=TAU recomputed with the exact
// fp32 ascending-i FMA chain from global x/W, bias after,
// bit = fl(0.5 + 0.25 z) > 0.5 (XLA rule) -> leaf indices bit-identical.

#define THREADS 128
#define TILES 16
#define TROWS 64
#define NBLK 1024          // 1048576 / (16*64)
#define TAU 5e-4f

// ---- shared layout (bytes) ----
// XB[2] : f32[64][68] x2 = 17408*2 = 34816 @ 0     (row stride 272B, 16B-aligned)
// Whp   : u32[48][36]     =  6912 @ 34816
// Wlp   : u32[48][36]     =  6912 @ 41728
// tbl   : float2[512]     =  4096 @ 48640
// bs    : f32[48]         =   192 @ 52736
#define XB_OFF   0
#define XB_STRIDE 17408
#define WHP_OFF  34816
#define WLP_OFF  41728
#define TBL_OFF  48640
#define BS_OFF   52736
#define SMEM_BYTES 52928

static __device__ __forceinline__ uint32_t smem_u32(const void* p) {
    uint32_t a;
    asm("{ .reg .u64 t; cvta.to.shared.u64 t, %1; cvt.u32.u64 %0, t; }"
        : "=r"(a) : "l"(p));
    return a;
}
static __device__ __forceinline__ uint32_t bf16x2_rn(float hi, float lo) {
    uint32_t r;
    asm("cvt.rn.bf16x2.f32 %0, %1, %2;" : "=r"(r) : "f"(hi), "f"(lo));
    return r;
}
static __device__ __forceinline__ void split2(float vx, float vy,
                                              uint32_t& h, uint32_t& l) {
    h = bf16x2_rn(vy, vx);
    float h0 = __uint_as_float(h << 16);
    float h1 = __uint_as_float(h & 0xffff0000u);
    l = bf16x2_rn(vy - h1, vx - h0);
}
static __device__ __forceinline__ void mma_bf16(float* c, const uint32_t* a,
                                                const uint32_t* b) {
    asm("mma.sync.aligned.m16n8k16.row.col.f32.bf16.bf16.f32 "
        "{%0,%1,%2,%3}, {%4,%5,%6,%7}, {%8,%9}, {%0,%1,%2,%3};"
        : "+f"(c[0]), "+f"(c[1]), "+f"(c[2]), "+f"(c[3])
        : "r"(a[0]), "r"(a[1]), "r"(a[2]), "r"(a[3]), "r"(b[0]), "r"(b[1]));
}
static __device__ __forceinline__ int xla_bit(float z) {
    return __fadd_rn(0.5f, __fmul_rn(0.25f, z)) > 0.5f;
}
#define CP16(dst, src) \
    asm volatile("cp.async.cg.shared.global [%0], [%1], 16;" \
                 :: "r"(dst), "l"(src) : "memory")
#define CP_COMMIT() asm volatile("cp.async.commit_group;" ::: "memory")
#define CP_WAIT1()  asm volatile("cp.async.wait_group 1;" ::: "memory")
#define CP_WAIT0()  asm volatile("cp.async.wait_group 0;" ::: "memory")

__global__ __launch_bounds__(THREADS, 4)
void node_forest_mma_kernel(const float*  __restrict__ x,      // [B,64]
                            const float*  __restrict__ Wsel,   // [48,64]
                            const float*  __restrict__ bsel,   // [48]
                            const float*  __restrict__ leafv,  // [8,64,2]
                            const float*  __restrict__ fcw,    // [2,16]
                            const float*  __restrict__ fcb,    // [2]
                            float2*       __restrict__ out)    // [B]
{
    extern __shared__ unsigned char smem[];
    uint32_t* Whp = (uint32_t*)(smem + WHP_OFF);
    uint32_t* Wlp = (uint32_t*)(smem + WLP_OFF);
    float2*   tbl = (float2*)(smem + TBL_OFF);
    float*    bs  = (float*)(smem + BS_OFF);

    const int tid = threadIdx.x;
    const uint32_t sbase = smem_u32(smem);

    // ---- prologue: W hi/lo tiles, leaf table fold, bias ----
    #pragma unroll
    for (int e = tid; e < 1536; e += THREADS) {
        int d = e >> 5, ip = e & 31;
        float2 wp = *(const float2*)(Wsel + d * 64 + 2 * ip);
        uint32_t h, l;
        split2(wp.x, wp.y, h, l);
        Whp[d * 36 + ip] = h;
        Wlp[d * 36 + ip] = l;
    }
    #pragma unroll
    for (int e = tid; e < 512; e += THREADS) {
        int t = e >> 6, leaf = e & 63;
        float l0 = leafv[t * 128 + leaf * 2 + 0];
        float l1 = leafv[t * 128 + leaf * 2 + 1];
        tbl[e] = make_float2(l0 * fcw[t * 2]      + l1 * fcw[t * 2 + 1],
                             l0 * fcw[16 + t * 2] + l1 * fcw[16 + t * 2 + 1]);
    }
    if (tid < 48) bs[tid] = bsel[tid];
    __syncthreads();

    const int lane = tid & 31, w = tid >> 5;
    const int g = lane >> 2, tig = lane & 3;
    const float fb0 = __ldg(&fcb[0]), fb1 = __ldg(&fcb[1]);
    const int row8 = tid >> 4, c4_2 = (tid & 15);  // staging map helpers

    // issue tile 0 into buffer 0
    {
        const float* src = x + ((size_t)(blockIdx.x * TILES) << 12);
        uint32_t dst = sbase + XB_OFF;
        #pragma unroll
        for (int it = 0; it < 8; ++it) {
            int f = tid + it * THREADS;          // 16B-chunk index (0..1023)
            int r = f >> 4, c4 = f & 15;
            CP16(dst + r * 272 + c4 * 16, src + r * 64 + c4 * 4);
        }
        CP_COMMIT();
    }

    #pragma unroll 1
    for (int tt = 0; tt < TILES; ++tt) {
        const size_t tile = (size_t)blockIdx.x * TILES + tt;
        const float* gxt = x + (tile << 12);     // tile * 64 * 64

        // issue next tile into the other buffer (overlaps this tile's compute)
        if (tt + 1 < TILES) {
            const float* src = gxt + 4096;
            uint32_t dst = sbase + XB_OFF + ((tt + 1) & 1) * XB_STRIDE;
            #pragma unroll
            for (int it = 0; it < 8; ++it) {
                int f = tid + it * THREADS;
                int r = f >> 4, c4 = f & 15;
                CP16(dst + r * 272 + c4 * 16, src + r * 64 + c4 * 4);
            }
            CP_COMMIT();
            CP_WAIT1();
        } else {
            CP_WAIT0();
        }
        __syncthreads();

        const float* xb = (const float*)(smem + XB_OFF + (tt & 1) * XB_STRIDE);

        float acc[6][4];
        #pragma unroll
        for (int n = 0; n < 6; ++n)
            #pragma unroll
            for (int q = 0; q < 4; ++q) acc[n][q] = 0.f;

        const int ra = w * 16 + g, rb = ra + 8;

        // ---- mainloop: LDS x from smem, split, HMMA ----
        #pragma unroll
        for (int kt = 0; kt < 4; ++kt) {
            uint32_t bh[6][2], bl[6][2];
            #pragma unroll
            for (int n = 0; n < 6; ++n) {
                int ip0 = (n * 8 + g) * 36 + kt * 8 + tig;
                bh[n][0] = Whp[ip0];  bh[n][1] = Whp[ip0 + 4];
                bl[n][0] = Wlp[ip0];  bl[n][1] = Wlp[ip0 + 4];
            }
            int c0 = kt * 16 + tig * 2;
            float2 p0 = *(const float2*)(xb + ra * 68 + c0);
            float2 p1 = *(const float2*)(xb + rb * 68 + c0);
            float2 p2 = *(const float2*)(xb + ra * 68 + c0 + 8);
            float2 p3 = *(const float2*)(xb + rb * 68 + c0 + 8);
            uint32_t ah[4], al[4];
            split2(p0.x, p0.y, ah[0], al[0]);
            split2(p1.x, p1.y, ah[1], al[1]);
            split2(p2.x, p2.y, ah[2], al[2]);
            split2(p3.x, p3.y, ah[3], al[3]);
            #pragma unroll
            for (int n = 0; n < 6; ++n) {
                mma_bf16(acc[n], ah, bh[n]);
                mma_bf16(acc[n], ah, bl[n]);
                mma_bf16(acc[n], al, bh[n]);
            }
        }
        __syncthreads();   // all warps done reading this buffer

        // ---- epilogue: bias, recompute band (rare), bit masks ----
        unsigned long long mask[2] = {0ull, 0ull};
        #pragma unroll
        for (int half = 0; half < 2; ++half) {
            int row = w * 16 + half * 8 + g;
            #pragma unroll
            for (int n = 0; n < 6; ++n) {
                #pragma unroll
                for (int e = 0; e < 2; ++e) {
                    int col = n * 8 + tig * 2 + e;
                    float z = __fadd_rn(acc[n][2 * half + e], bs[col]);
                    if (fabsf(z) <= TAU) {
                        const float4* xr = (const float4*)(gxt + row * 64);
                        const float4* wr = (const float4*)(Wsel + col * 64);
                        float a = 0.f;
                        #pragma unroll 1
                        for (int i4 = 0; i4 < 16; ++i4) {
                            float4 xa = __ldg(xr + i4);
                            float4 wa = __ldg(wr + i4);
                            a = __fmaf_rn(xa.x, wa.x, a);
                            a = __fmaf_rn(xa.y, wa.y, a);
                            a = __fmaf_rn(xa.z, wa.z, a);
                            a = __fmaf_rn(xa.w, wa.w, a);
                        }
                        z = __fadd_rn(a, bs[col]);
                    }
                    mask[half] |= ((unsigned long long)xla_bit(z)) << col;
                }
            }
        }
        #pragma unroll
        for (int half = 0; half < 2; ++half) {
            unsigned long long v = mask[half];
            v |= __shfl_xor_sync(0xffffffffu, v, 1);
            v |= __shfl_xor_sync(0xffffffffu, v, 2);
            mask[half] = v;
        }
        if (tig < 2) {
            const unsigned long long mk = mask[tig];
            const int row = w * 16 + tig * 8 + g;
            float o0 = fb0, o1 = fb1;
            #pragma unroll
            for (int t = 0; t < 8; ++t) {
                int bits6 = (int)(mk >> (6 * t)) & 63;
                int leaf = __brev((unsigned)bits6) >> 26;
                float2 tv = tbl[t * 64 + leaf];
                o0 += tv.x;
                o1 += tv.y;
            }
            out[tile * TROWS + row] = make_float2(o0, o1);
        }
    }
}

extern "C" void kernel_launch(void* const* d_in, const int* in_sizes, int n_in,
                              void* d_out, int out_size) {
    (void)in_sizes; (void)n_in; (void)out_size;
    cudaFuncSetAttribute(node_forest_mma_kernel,
                         cudaFuncAttributeMaxDynamicSharedMemorySize, SMEM_BYTES);
    cudaFuncSetAttribute(node_forest_mma_kernel,
                         cudaFuncAttributePreferredSharedMemoryCarveout, 100);
    node_forest_mma_kernel<<<NBLK, THREADS, SMEM_BYTES>>>(
        (const float*)d_in[0],   // x
        (const float*)d_in[1],   // W_sel
        (const float*)d_in[2],   // b_sel
        (const float*)d_in[3],   // leaf_values
        (const float*)d_in[4],   // fc_w
        (const float*)d_in[5],   // fc_b
        (float2*)d_out);
}

// round 14
// speedup vs baseline: 2.9295x; 1.3263x over previous
#include <cuda_runtime.h>
#include <cuda_bf16.h>
#include <cstdint>

// NODE forest via mma.sync bf16 (plain compute_103 PTX).
// R14: warp-autonomous pipeline. Each warp owns a private 16-row x strip
// (2-deep cp.async ring) and free-runs 16 strips with NO CTA barriers in
// the main loop (cp.async groups are per-thread; __syncwarp suffices).
// R13's two __syncthreads per tile were costing ~40% of wall time.
//
// Numerics (proven R9-R13, rel_err 9.227e-8): 3-pass bf16 split
// (Ah*Wh + Ah*Wl + Al*Wh, fp32 accum); |z|<=TAU=5e-4 (hard bound 2.6e-4)
// recomputed with the exact fp32 ascending-i FMA chain, bias after,
// bit = fl(0.5 + 0.25 z) > 0.5 (XLA rule) -> leaf indices bit-identical.

#define THREADS 128
#define STRIPS 16          // strips per warp, 16 rows each
#define NBLK 1024          // 1048576 / (4 warps * 16 strips * 16 rows)
#define TAU 5e-4f

// ---- shared layout (bytes) ----
// XB  : 4 warps x 2 bufs x [16 rows][68 f32] = 4*2*4352 = 34816 @ 0
// Whp : u32[48][36] = 6912 @ 34816
// Wlp : u32[48][36] = 6912 @ 41728
// tbl : float2[512] = 4096 @ 48640
// bs  : f32[48]     =  192 @ 52736
#define XB_OFF   0
#define XB_WARP  8704      // 2 buffers per warp
#define XB_BUF   4352      // 16 rows * 272B
#define WHP_OFF  34816
#define WLP_OFF  41728
#define TBL_OFF  48640
#define BS_OFF   52736
#define SMEM_BYTES 52928

static __device__ __forceinline__ uint32_t smem_u32(const void* p) {
    uint32_t a;
    asm("{ .reg .u64 t; cvta.to.shared.u64 t, %1; cvt.u32.u64 %0, t; }"
        : "=r"(a) : "l"(p));
    return a;
}
static __device__ __forceinline__ uint32_t bf16x2_rn(float hi, float lo) {
    uint32_t r;
    asm("cvt.rn.bf16x2.f32 %0, %1, %2;" : "=r"(r) : "f"(hi), "f"(lo));
    return r;
}
static __device__ __forceinline__ void split2(float vx, float vy,
                                              uint32_t& h, uint32_t& l) {
    h = bf16x2_rn(vy, vx);
    float h0 = __uint_as_float(h << 16);
    float h1 = __uint_as_float(h & 0xffff0000u);
    l = bf16x2_rn(vy - h1, vx - h0);
}
static __device__ __forceinline__ void mma_bf16(float* c, const uint32_t* a,
                                                const uint32_t* b) {
    asm("mma.sync.aligned.m16n8k16.row.col.f32.bf16.bf16.f32 "
        "{%0,%1,%2,%3}, {%4,%5,%6,%7}, {%8,%9}, {%0,%1,%2,%3};"
        : "+f"(c[0]), "+f"(c[1]), "+f"(c[2]), "+f"(c[3])
        : "r"(a[0]), "r"(a[1]), "r"(a[2]), "r"(a[3]), "r"(b[0]), "r"(b[1]));
}
static __device__ __forceinline__ int xla_bit(float z) {
    return __fadd_rn(0.5f, __fmul_rn(0.25f, z)) > 0.5f;
}
#define CP16(dst, src) \
    asm volatile("cp.async.cg.shared.global [%0], [%1], 16;" \
                 :: "r"(dst), "l"(src) : "memory")
#define CP_COMMIT() asm volatile("cp.async.commit_group;" ::: "memory")
#define CP_WAIT1()  asm volatile("cp.async.wait_group 1;" ::: "memory")
#define CP_WAIT0()  asm volatile("cp.async.wait_group 0;" ::: "memory")

__global__ __launch_bounds__(THREADS, 4)
void node_forest_mma_kernel(const float*  __restrict__ x,      // [B,64]
                            const float*  __restrict__ Wsel,   // [48,64]
                            const float*  __restrict__ bsel,   // [48]
                            const float*  __restrict__ leafv,  // [8,64,2]
                            const float*  __restrict__ fcw,    // [2,16]
                            const float*  __restrict__ fcb,    // [2]
                            float2*       __restrict__ out)    // [B]
{
    extern __shared__ unsigned char smem[];
    uint32_t* Whp = (uint32_t*)(smem + WHP_OFF);
    uint32_t* Wlp = (uint32_t*)(smem + WLP_OFF);
    float2*   tbl = (float2*)(smem + TBL_OFF);
    float*    bs  = (float*)(smem + BS_OFF);

    const int tid = threadIdx.x;
    const uint32_t sbase = smem_u32(smem);

    // ---- prologue (once per CTA): W hi/lo tiles, table fold, bias ----
    #pragma unroll
    for (int e = tid; e < 1536; e += THREADS) {
        int d = e >> 5, ip = e & 31;
        float2 wp = *(const float2*)(Wsel + d * 64 + 2 * ip);
        uint32_t h, l;
        split2(wp.x, wp.y, h, l);
        Whp[d * 36 + ip] = h;
        Wlp[d * 36 + ip] = l;
    }
    #pragma unroll
    for (int e = tid; e < 512; e += THREADS) {
        int t = e >> 6, leaf = e & 63;
        float l0 = leafv[t * 128 + leaf * 2 + 0];
        float l1 = leafv[t * 128 + leaf * 2 + 1];
        tbl[e] = make_float2(l0 * fcw[t * 2]      + l1 * fcw[t * 2 + 1],
                             l0 * fcw[16 + t * 2] + l1 * fcw[16 + t * 2 + 1]);
    }
    if (tid < 48) bs[tid] = bsel[tid];
    __syncthreads();   // the ONLY CTA barrier

    const int lane = tid & 31, w = tid >> 5;
    const int g = lane >> 2, tig = lane & 3;
    const float fb0 = __ldg(&fcb[0]), fb1 = __ldg(&fcb[1]);

    // this warp's strips: gstrip = wbase + ss
    const size_t wbase = ((size_t)blockIdx.x * 4 + w) * STRIPS;
    const uint32_t xbw = sbase + XB_OFF + w * XB_WARP;   // warp's 2 buffers

    // issue strip 0 into buffer 0 (16 rows x 64 f32 = 256 x 16B chunks)
    {
        const float* src = x + (wbase << 10);
        #pragma unroll
        for (int it = 0; it < 8; ++it) {
            int f = lane + it * 32;
            int r = f >> 4, c4 = f & 15;
            CP16(xbw + r * 272 + c4 * 16, src + r * 64 + c4 * 4);
        }
        CP_COMMIT();
    }

    #pragma unroll 1
    for (int ss = 0; ss < STRIPS; ++ss) {
        const size_t gstrip = wbase + ss;

        if (ss + 1 < STRIPS) {
            const float* src = x + ((gstrip + 1) << 10);
            uint32_t dst = xbw + ((ss + 1) & 1) * XB_BUF;
            #pragma unroll
            for (int it = 0; it < 8; ++it) {
                int f = lane + it * 32;
                int r = f >> 4, c4 = f & 15;
                CP16(dst + r * 272 + c4 * 16, src + r * 64 + c4 * 4);
            }
            CP_COMMIT();
            CP_WAIT1();
        } else {
            CP_WAIT0();
        }
        __syncwarp();

        const float* xb = (const float*)(smem + XB_OFF + w * XB_WARP
                                              + (ss & 1) * XB_BUF);

        float acc[6][4];
        #pragma unroll
        for (int n = 0; n < 6; ++n)
            #pragma unroll
            for (int q = 0; q < 4; ++q) acc[n][q] = 0.f;

        // ---- mainloop: LDS x, split, HMMA (rows g and g+8 of the strip) ----
        #pragma unroll
        for (int kt = 0; kt < 4; ++kt) {
            uint32_t bh[6][2], bl[6][2];
            #pragma unroll
            for (int n = 0; n < 6; ++n) {
                int ip0 = (n * 8 + g) * 36 + kt * 8 + tig;
                bh[n][0] = Whp[ip0];  bh[n][1] = Whp[ip0 + 4];
                bl[n][0] = Wlp[ip0];  bl[n][1] = Wlp[ip0 + 4];
            }
            int c0 = kt * 16 + tig * 2;
            float2 p0 = *(const float2*)(xb + g * 68 + c0);
            float2 p1 = *(const float2*)(xb + (g + 8) * 68 + c0);
            float2 p2 = *(const float2*)(xb + g * 68 + c0 + 8);
            float2 p3 = *(const float2*)(xb + (g + 8) * 68 + c0 + 8);
            uint32_t ah[4], al[4];
            split2(p0.x, p0.y, ah[0], al[0]);
            split2(p1.x, p1.y, ah[1], al[1]);
            split2(p2.x, p2.y, ah[2], al[2]);
            split2(p3.x, p3.y, ah[3], al[3]);
            #pragma unroll
            for (int n = 0; n < 6; ++n) {
                mma_bf16(acc[n], ah, bh[n]);
                mma_bf16(acc[n], ah, bl[n]);
                mma_bf16(acc[n], al, bh[n]);
            }
        }

        // ---- epilogue: bias, band recompute (from smem x), bit masks ----
        unsigned long long mask[2] = {0ull, 0ull};
        #pragma unroll
        for (int half = 0; half < 2; ++half) {
            int row = half * 8 + g;                     // row within strip
            #pragma unroll
            for (int n = 0; n < 6; ++n) {
                #pragma unroll
                for (int e = 0; e < 2; ++e) {
                    int col = n * 8 + tig * 2 + e;
                    float z = __fadd_rn(acc[n][2 * half + e], bs[col]);
                    if (fabsf(z) <= TAU) {
                        // exact fp32 ascending-i chain (bit-faithful)
                        const float4* xr = (const float4*)(xb + row * 68);
                        const float4* wr = (const float4*)(Wsel + col * 64);
                        float a = 0.f;
                        #pragma unroll 1
                        for (int i4 = 0; i4 < 16; ++i4) {
                            float4 xa = xr[i4];
                            float4 wa = __ldg(wr + i4);
                            a = __fmaf_rn(xa.x, wa.x, a);
                            a = __fmaf_rn(xa.y, wa.y, a);
                            a = __fmaf_rn(xa.z, wa.z, a);
                            a = __fmaf_rn(xa.w, wa.w, a);
                        }
                        z = __fadd_rn(a, bs[col]);
                    }
                    mask[half] |= ((unsigned long long)xla_bit(z)) << col;
                }
            }
        }
        #pragma unroll
        for (int half = 0; half < 2; ++half) {
            unsigned long long v = mask[half];
            v |= __shfl_xor_sync(0xffffffffu, v, 1);
            v |= __shfl_xor_sync(0xffffffffu, v, 2);
            mask[half] = v;
        }
        if (tig < 2) {
            const unsigned long long mk = mask[tig];
            const int row = tig * 8 + g;
            float o0 = fb0, o1 = fb1;
            #pragma unroll
            for (int t = 0; t < 8; ++t) {
                int bits6 = (int)(mk >> (6 * t)) & 63;
                int leaf = __brev((unsigned)bits6) >> 26;
                float2 tv = tbl[t * 64 + leaf];
                o0 += tv.x;
                o1 += tv.y;
            }
            out[gstrip * 16 + row] = make_float2(o0, o1);
        }
        __syncwarp();   // all lanes done reading xb before next cp overwrite
    }
}

extern "C" void kernel_launch(void* const* d_in, const int* in_sizes, int n_in,
                              void* d_out, int out_size) {
    (void)in_sizes; (void)n_in; (void)out_size;
    cudaFuncSetAttribute(node_forest_mma_kernel,
                         cudaFuncAttributeMaxDynamicSharedMemorySize, SMEM_BYTES);
    cudaFuncSetAttribute(node_forest_mma_kernel,
                         cudaFuncAttributePreferredSharedMemoryCarveout, 100);
    node_forest_mma_kernel<<<NBLK, THREADS, SMEM_BYTES>>>(
        (const float*)d_in[0],   // x
        (const float*)d_in[1],   // W_sel
        (const float*)d_in[2],   // b_sel
        (const float*)d_in[3],   // leaf_values
        (const float*)d_in[4],   // fc_w
        (const float*)d_in[5],   // fc_b
        (float2*)d_out);
}

// round 15
// speedup vs baseline: 3.2421x; 1.1067x over previous
#include <cuda_runtime.h>
#include <cuda_bf16.h>
#include <cstdint>

// NODE forest via mma.sync bf16 (plain compute_103 PTX).
// R15 = R14 (warp-autonomous cp.async pipeline, no CTA barriers in mainloop)
// with an epilogue diet:
//  - bit rule: fl(0.5+0.25z)>0.5  ==  z > 2^-23  (exact identity, proven)
//  - two u32 masks instead of u64 (cheap shifts/ors)
//  - bias in registers; leaf gather spread over all 4 quad lanes
//
// Numerics: 3-pass bf16 split (Ah*Wh + Ah*Wl + Al*Wh, fp32 accum), hard
// error bound 2.6e-4 << TAU=5e-4; |z|<=TAU recomputed with the exact fp32
// ascending-i FMA chain (bias after). Leaf indices bit-identical to ref.

#define THREADS 128
#define STRIPS 16
#define NBLK 1024
#define TAU 5e-4f
#define ZTHR 1.1920928955078125e-7f   // 2^-23

// ---- shared layout (bytes) ----
#define XB_OFF   0          // 4 warps x 2 bufs x [16][68] f32 = 34816
#define XB_WARP  8704
#define XB_BUF   4352
#define WHP_OFF  34816      // u32[48][36] = 6912
#define WLP_OFF  41728      // u32[48][36] = 6912
#define TBL_OFF  48640      // float2[512] = 4096
#define BS_OFF   52736      // f32[48]
#define SMEM_BYTES 52928

static __device__ __forceinline__ uint32_t smem_u32(const void* p) {
    uint32_t a;
    asm("{ .reg .u64 t; cvta.to.shared.u64 t, %1; cvt.u32.u64 %0, t; }"
        : "=r"(a) : "l"(p));
    return a;
}
static __device__ __forceinline__ uint32_t bf16x2_rn(float hi, float lo) {
    uint32_t r;
    asm("cvt.rn.bf16x2.f32 %0, %1, %2;" : "=r"(r) : "f"(hi), "f"(lo));
    return r;
}
static __device__ __forceinline__ void split2(float vx, float vy,
                                              uint32_t& h, uint32_t& l) {
    h = bf16x2_rn(vy, vx);
    float h0 = __uint_as_float(h << 16);
    float h1 = __uint_as_float(h & 0xffff0000u);
    l = bf16x2_rn(vy - h1, vx - h0);
}
static __device__ __forceinline__ void mma_bf16(float* c, const uint32_t* a,
                                                const uint32_t* b) {
    asm("mma.sync.aligned.m16n8k16.row.col.f32.bf16.bf16.f32 "
        "{%0,%1,%2,%3}, {%4,%5,%6,%7}, {%8,%9}, {%0,%1,%2,%3};"
        : "+f"(c[0]), "+f"(c[1]), "+f"(c[2]), "+f"(c[3])
        : "r"(a[0]), "r"(a[1]), "r"(a[2]), "r"(a[3]), "r"(b[0]), "r"(b[1]));
}
#define CP16(dst, src) \
    asm volatile("cp.async.cg.shared.global [%0], [%1], 16;" \
                 :: "r"(dst), "l"(src) : "memory")
#define CP_COMMIT() asm volatile("cp.async.commit_group;" ::: "memory")
#define CP_WAIT1()  asm volatile("cp.async.wait_group 1;" ::: "memory")
#define CP_WAIT0()  asm volatile("cp.async.wait_group 0;" ::: "memory")

__global__ __launch_bounds__(THREADS, 4)
void node_forest_mma_kernel(const float*  __restrict__ x,      // [B,64]
                            const float*  __restrict__ Wsel,   // [48,64]
                            const float*  __restrict__ bsel,   // [48]
                            const float*  __restrict__ leafv,  // [8,64,2]
                            const float*  __restrict__ fcw,    // [2,16]
                            const float*  __restrict__ fcb,    // [2]
                            float2*       __restrict__ out)    // [B]
{
    extern __shared__ unsigned char smem[];
    uint32_t* Whp = (uint32_t*)(smem + WHP_OFF);
    uint32_t* Wlp = (uint32_t*)(smem + WLP_OFF);
    float2*   tbl = (float2*)(smem + TBL_OFF);
    float*    bs  = (float*)(smem + BS_OFF);

    const int tid = threadIdx.x;
    const uint32_t sbase = smem_u32(smem);

    // ---- prologue (once per CTA): W hi/lo tiles, table fold, bias ----
    #pragma unroll
    for (int e = tid; e < 1536; e += THREADS) {
        int d = e >> 5, ip = e & 31;
        float2 wp = *(const float2*)(Wsel + d * 64 + 2 * ip);
        uint32_t h, l;
        split2(wp.x, wp.y, h, l);
        Whp[d * 36 + ip] = h;
        Wlp[d * 36 + ip] = l;
    }
    #pragma unroll
    for (int e = tid; e < 512; e += THREADS) {
        int t = e >> 6, leaf = e & 63;
        float l0 = leafv[t * 128 + leaf * 2 + 0];
        float l1 = leafv[t * 128 + leaf * 2 + 1];
        tbl[e] = make_float2(l0 * fcw[t * 2]      + l1 * fcw[t * 2 + 1],
                             l0 * fcw[16 + t * 2] + l1 * fcw[16 + t * 2 + 1]);
    }
    if (tid < 48) bs[tid] = bsel[tid];
    __syncthreads();   // the ONLY CTA barrier

    const int lane = tid & 31, w = tid >> 5;
    const int g = lane >> 2, tig = lane & 3;
    const int t2 = tig * 2;
    const float fb0 = __ldg(&fcb[0]), fb1 = __ldg(&fcb[1]);

    // bias for this lane's 12 columns, held in registers for all strips
    float bb[12];
    #pragma unroll
    for (int n = 0; n < 6; ++n) {
        bb[n * 2]     = bs[n * 8 + t2];
        bb[n * 2 + 1] = bs[n * 8 + t2 + 1];
    }

    const size_t wbase = ((size_t)blockIdx.x * 4 + w) * STRIPS;
    const uint32_t xbw = sbase + XB_OFF + w * XB_WARP;

    // issue strip 0 into buffer 0
    {
        const float* src = x + (wbase << 10);
        #pragma unroll
        for (int it = 0; it < 8; ++it) {
            int f = lane + it * 32;
            int r = f >> 4, c4 = f & 15;
            CP16(xbw + r * 272 + c4 * 16, src + r * 64 + c4 * 4);
        }
        CP_COMMIT();
    }

    #pragma unroll 1
    for (int ss = 0; ss < STRIPS; ++ss) {
        const size_t gstrip = wbase + ss;

        if (ss + 1 < STRIPS) {
            const float* src = x + ((gstrip + 1) << 10);
            uint32_t dst = xbw + ((ss + 1) & 1) * XB_BUF;
            #pragma unroll
            for (int it = 0; it < 8; ++it) {
                int f = lane + it * 32;
                int r = f >> 4, c4 = f & 15;
                CP16(dst + r * 272 + c4 * 16, src + r * 64 + c4 * 4);
            }
            CP_COMMIT();
            CP_WAIT1();
        } else {
            CP_WAIT0();
        }
        __syncwarp();

        const float* xb = (const float*)(smem + XB_OFF + w * XB_WARP
                                              + (ss & 1) * XB_BUF);

        float acc[6][4];
        #pragma unroll
        for (int n = 0; n < 6; ++n)
            #pragma unroll
            for (int q = 0; q < 4; ++q) acc[n][q] = 0.f;

        // ---- mainloop: LDS x, split, HMMA ----
        #pragma unroll
        for (int kt = 0; kt < 4; ++kt) {
            uint32_t bh[6][2], bl[6][2];
            #pragma unroll
            for (int n = 0; n < 6; ++n) {
                int ip0 = (n * 8 + g) * 36 + kt * 8 + tig;
                bh[n][0] = Whp[ip0];  bh[n][1] = Whp[ip0 + 4];
                bl[n][0] = Wlp[ip0];  bl[n][1] = Wlp[ip0 + 4];
            }
            int c0 = kt * 16 + t2;
            float2 p0 = *(const float2*)(xb + g * 68 + c0);
            float2 p1 = *(const float2*)(xb + (g + 8) * 68 + c0);
            float2 p2 = *(const float2*)(xb + g * 68 + c0 + 8);
            float2 p3 = *(const float2*)(xb + (g + 8) * 68 + c0 + 8);
            uint32_t ah[4], al[4];
            split2(p0.x, p0.y, ah[0], al[0]);
            split2(p1.x, p1.y, ah[1], al[1]);
            split2(p2.x, p2.y, ah[2], al[2]);
            split2(p3.x, p3.y, ah[3], al[3]);
            #pragma unroll
            for (int n = 0; n < 6; ++n) {
                mma_bf16(acc[n], ah, bh[n]);
                mma_bf16(acc[n], ah, bl[n]);
                mma_bf16(acc[n], al, bh[n]);
            }
        }

        // ---- epilogue: z, band recompute (rare), two-u32 bit masks ----
        uint32_t mlo[2] = {0u, 0u}, mhi[2] = {0u, 0u};
        #pragma unroll
        for (int half = 0; half < 2; ++half) {
            int row = half * 8 + g;
            #pragma unroll
            for (int n = 0; n < 6; ++n) {
                #pragma unroll
                for (int e = 0; e < 2; ++e) {
                    float z = __fadd_rn(acc[n][2 * half + e], bb[n * 2 + e]);
                    if (fabsf(z) <= TAU) {
                        // exact fp32 ascending-i chain (bit-faithful)
                        int col = n * 8 + t2 + e;
                        const float4* xr = (const float4*)(xb + row * 68);
                        const float4* wr = (const float4*)(Wsel + col * 64);
                        float a = 0.f;
                        #pragma unroll 1
                        for (int i4 = 0; i4 < 16; ++i4) {
                            float4 xa = xr[i4];
                            float4 wa = __ldg(wr + i4);
                            a = __fmaf_rn(xa.x, wa.x, a);
                            a = __fmaf_rn(xa.y, wa.y, a);
                            a = __fmaf_rn(xa.z, wa.z, a);
                            a = __fmaf_rn(xa.w, wa.w, a);
                        }
                        z = __fadd_rn(a, bb[n * 2 + e]);
                    }
                    uint32_t bit = (z > ZTHR) ? 1u : 0u;   // == XLA sigmoid rule
                    if (n < 3) mlo[half] |= bit << (n * 8 + t2 + e);
                    else       mhi[half] |= bit << ((n - 3) * 8 + t2 + e);
                }
            }
        }
        #pragma unroll
        for (int half = 0; half < 2; ++half) {
            mlo[half] |= __shfl_xor_sync(0xffffffffu, mlo[half], 1);
            mhi[half] |= __shfl_xor_sync(0xffffffffu, mhi[half], 1);
            mlo[half] |= __shfl_xor_sync(0xffffffffu, mlo[half], 2);
            mhi[half] |= __shfl_xor_sync(0xffffffffu, mhi[half], 2);
        }

        // distributed leaf gather: lane tig -> half = tig&1, trees grp*4..+3
        {
            const int h = tig & 1, grp = tig >> 1;
            uint32_t m = grp ? mhi[h] : mlo[h];
            float o0 = 0.f, o1 = 0.f;
            #pragma unroll
            for (int t = 0; t < 4; ++t) {
                int bits6 = (int)(m >> (6 * t)) & 63;
                int leaf = __brev((unsigned)bits6) >> 26;
                float2 tv = tbl[(grp * 4 + t) * 64 + leaf];
                o0 += tv.x;
                o1 += tv.y;
            }
            o0 += __shfl_xor_sync(0xffffffffu, o0, 2);
            o1 += __shfl_xor_sync(0xffffffffu, o1, 2);
            if (tig < 2)
                out[gstrip * 16 + tig * 8 + g] = make_float2(o0 + fb0,
                                                             o1 + fb1);
        }
        __syncwarp();   // xb fully consumed before next cp.async overwrite
    }
}

extern "C" void kernel_launch(void* const* d_in, const int* in_sizes, int n_in,
                              void* d_out, int out_size) {
    (void)in_sizes; (void)n_in; (void)out_size;
    cudaFuncSetAttribute(node_forest_mma_kernel,
                         cudaFuncAttributeMaxDynamicSharedMemorySize, SMEM_BYTES);
    cudaFuncSetAttribute(node_forest_mma_kernel,
                         cudaFuncAttributePreferredSharedMemoryCarveout, 100);
    node_forest_mma_kernel<<<NBLK, THREADS, SMEM_BYTES>>>(
        (const float*)d_in[0],   // x
        (const float*)d_in[1],   // W_sel
        (const float*)d_in[2],   // b_sel
        (const float*)d_in[3],   // leaf_values
        (const float*)d_in[4],   // fc_w
        (const float*)d_in[5],   // fc_b
        (float2*)d_out);
}